// round 11
// baseline (speedup 1.0000x reference)
#include <cuda_runtime.h>
#include <cuda_fp16.h>
#include <math.h>
#include <stdint.h>

#define NB 2
#define LQ 2048
#define SK 2048
#define HH 8
#define DD 64
#define NHT (NB*HH)
#define NHLD (NB*HH*LQ*DD)   // 2,097,152
#define NROWS (NHT*LQ)       // 32768
#define ZSPLIT 4
#define TILES_PER_CTA 4

// Scratch: phiK fp16 [n][h][s][d]; K partial sums; row maxima
__device__ __align__(256) __half g_Kh[NHLD];
__device__ __align__(256) float g_kpart[512*DD];    // 32 blocks per nh
__device__ __align__(256) unsigned int g_rowmax[NROWS];

// ---------------------------------------------------------------------------
// PTX helpers
// ---------------------------------------------------------------------------
__device__ __forceinline__ uint32_t smem_u32_of(const void* p) {
    uint32_t a;
    asm("{ .reg .u64 t; cvta.to.shared.u64 t, %1; cvt.u32.u64 %0, t; }" : "=r"(a) : "l"(p));
    return a;
}
#define LDM4(r, addr) \
    asm volatile("ldmatrix.sync.aligned.m8n8.x4.shared.b16 {%0,%1,%2,%3}, [%4];" \
        : "=r"((r)[0]), "=r"((r)[1]), "=r"((r)[2]), "=r"((r)[3]) : "r"(addr))
#define MMAF16(c, a0, a1, a2, a3, b0, b1) \
    asm volatile("mma.sync.aligned.m16n8k16.row.col.f32.f16.f16.f32 " \
        "{%0,%1,%2,%3}, {%4,%5,%6,%7}, {%8,%9}, {%0,%1,%2,%3};" \
        : "+f"((c)[0]), "+f"((c)[1]), "+f"((c)[2]), "+f"((c)[3]) \
        : "r"(a0), "r"(a1), "r"(a2), "r"(a3), "r"(b0), "r"(b1))
#define CPA16(s, g) \
    asm volatile("cp.async.cg.shared.global [%0], [%1], 16;" :: "r"(s), "l"(g))
#define CPC()  asm volatile("cp.async.commit_group;" ::: "memory")
#define CPW1() asm volatile("cp.async.wait_group 1;" ::: "memory")
#define CPW0() asm volatile("cp.async.wait_group 0;" ::: "memory")

__device__ __forceinline__ float phi(float x) {
    return (x > 0.f) ? (x + 1.f) : __expf(x);
}

// SMEM byte offsets (main kernel)
#define A_OFF 0
#define B_OFF 16384             // + (t%3)*16384, 3 stages
#define SMEM_TOTAL 65536

// ---------------------------------------------------------------------------
// Kernel A: K-only prep. feature map + mask + [n,s,h,d]->[n,h,s,d], fp16 out.
// 16 elements/thread; block covers 64 rows of one (n,h); per-block K partial
// sums into g_kpart[block][64]. Zeroes g_rowmax.  grid = 512.
// ---------------------------------------------------------------------------
__global__ __launch_bounds__(256) void prep_kernel(
    const float* __restrict__ k, const float* __restrict__ km)
{
    const int tid = threadIdx.x;
    const int idx = blockIdx.x * 256 + tid;        // 16-element chunk index
    if (idx < NROWS) g_rowmax[idx] = 0u;

    const int e = idx << 4;                        // first element
    const int d0 = e & 63;                         // 0,16,32,48
    const int l  = (e >> 6) & 2047;
    const int h  = (e >> 17) & 7;
    const int n  = e >> 20;
    const size_t src = ((((size_t)n * 2048 + l) * 8 + h) << 6) + d0;

    float4 v[4];
    v[0] = *(const float4*)(k + src);
    v[1] = *(const float4*)(k + src + 4);
    v[2] = *(const float4*)(k + src + 8);
    v[3] = *(const float4*)(k + src + 12);
    const float kmv = km[n * 2048 + l];

    float pk[16];
    uint4 o[2];
    uint32_t* po = (uint32_t*)o;
    #pragma unroll
    for (int j = 0; j < 4; j++) {
        const float* f = (const float*)&v[j];
        #pragma unroll
        for (int w = 0; w < 2; w++) {
            float ax = phi(f[2*w])   * kmv;
            float ay = phi(f[2*w+1]) * kmv;
            pk[j*4 + 2*w]   = ax;
            pk[j*4 + 2*w+1] = ay;
            __half2 hh = __floats2half2_rn(ax, ay);
            po[j*2 + w] = *(uint32_t*)&hh;
        }
    }
    ((uint4*)g_Kh)[idx*2]   = o[0];
    ((uint4*)g_Kh)[idx*2+1] = o[1];

    // --- block-local K partial sum: 64 rows x 64 d -> 64 floats ---
    __shared__ float stage[64][68];
    const int row = tid >> 2;                      // 0..63
    const int dc  = (tid & 3) * 16;
    #pragma unroll
    for (int j = 0; j < 4; j++)
        *(float4*)&stage[row][dc + j*4] = *(float4*)&pk[j*4];
    __syncthreads();
    if (tid < 64) {
        float s = 0.f;
        #pragma unroll
        for (int r = 0; r < 64; r++) s += stage[r][tid];
        g_kpart[blockIdx.x * 64 + tid] = s;
    }
}

// ---------------------------------------------------------------------------
// Kernel C: fp16 HMMA score GEMM + row-max via atomicMax.
// A tile (phiQ) computed INLINE from queries fp32 (L2-resident).
// grid=(16 ltile, 16 nh, ZSPLIT), block=256 (8 warps 4x2), 2 CTAs/SM.
// ---------------------------------------------------------------------------
__global__ void __launch_bounds__(256, 2) attn_mma_kernel(
    const float* __restrict__ queries,
    const float* __restrict__ qmask)
{
    extern __shared__ char sm[];
    const uint32_t smu = smem_u32_of(sm);

    const int tid  = threadIdx.x;
    const int lane = tid & 31;
    const int wid  = tid >> 5;
    const int wx   = wid & 1;       // n-block (64 cols)
    const int wy   = wid >> 1;      // m-block (32 rows)
    const int nh   = blockIdx.y;
    const int l0   = blockIdx.x * 128;
    const int ts0  = blockIdx.z * TILES_PER_CTA;
    const int n    = nh >> 3;
    const int h    = nh & 7;

    const int mat    = lane >> 3;
    const int rin    = lane & 7;
    const int a_row  = wy * 32 + (mat & 1) * 8 + rin;
    const int a_kc   = mat >> 1;
    const int b_roff = wx * 64 + (mat >> 1) * 8 + rin;
    const int b_kc   = mat & 1;

    const char* kh_base = (const char*)(g_Kh + (size_t)nh * SK * DD);

    auto issue_b = [&](int t) {
        uint32_t bu = smu + B_OFF + (t % 3) * 16384;
        const char* gk = kh_base + (size_t)(ts0 + t) * 128 * DD * 2;
        #pragma unroll
        for (int kk = 0; kk < 4; kk++) {
            int c = tid + kk * 256;
            int row = c >> 3, dc = c & 7;
            uint32_t sw = row * 128 + ((dc ^ (row & 7)) << 4);
            CPA16(bu + sw, gk + c * 16);
        }
    };

    issue_b(0); CPC();
    issue_b(1); CPC();

    // --- A tile: phi(queries)*qmask -> fp16, swizzled STS (overlaps cp.async) ---
    {
        const float* qrow = queries + ((((size_t)n * 2048 + l0) * 8 + h) << 6);
        const float* qmk  = qmask + n * 2048 + l0;
        #pragma unroll
        for (int c4 = 0; c4 < 4; c4++) {
            int c = tid + c4 * 256;            // 16B-out chunk, 0..1023
            int row = c >> 3, dc = c & 7;
            const float4* src = (const float4*)(qrow + (size_t)row * 512 + dc * 8);
            float4 v0 = src[0], v1 = src[1];
            float qmv = qmk[row];
            float f[8] = {v0.x, v0.y, v0.z, v0.w, v1.x, v1.y, v1.z, v1.w};
            uint4 o;
            uint32_t* po = (uint32_t*)&o;
            #pragma unroll
            for (int j = 0; j < 4; j++) {
                __half2 hh = __floats2half2_rn(phi(f[2*j]) * qmv, phi(f[2*j+1]) * qmv);
                po[j] = *(uint32_t*)&hh;
            }
            uint32_t dst = row * 128 + ((dc ^ (row & 7)) << 4);
            *(uint4*)(sm + A_OFF + dst) = o;
        }
    }

    float mA[2] = {0.f, 0.f};
    float mB[2] = {0.f, 0.f};

    for (int t = 0; t < TILES_PER_CTA; t++) {
        if (t + 1 < TILES_PER_CTA) { CPW1(); }
        else                       { CPW0(); }
        __syncthreads();                        // stage t + A visible; t-1 done
        if (t + 2 < TILES_PER_CTA) { issue_b(t + 2); CPC(); }

        const uint32_t Bu = smu + B_OFF + (t % 3) * 16384;
        float acc[2][8][4];
        #pragma unroll
        for (int i = 0; i < 2; i++)
            #pragma unroll
            for (int j = 0; j < 8; j++)
                acc[i][j][0] = acc[i][j][1] = acc[i][j][2] = acc[i][j][3] = 0.f;

        #pragma unroll
        for (int ks = 0; ks < 4; ks++) {
            const int kb = ks * 2;
            uint32_t ah[2][4];
            #pragma unroll
            for (int i = 0; i < 2; i++) {
                int ar = a_row + 16 * i;
                uint32_t ad = smu + A_OFF + ar * 128 + (((a_kc + kb) ^ (ar & 7)) << 4);
                LDM4(ah[i], ad);
            }
            uint32_t rb[4][4];
            #pragma unroll
            for (int jp = 0; jp < 4; jp++) {
                int br = b_roff + jp * 16;
                uint32_t bd = Bu + br * 128 + (((b_kc + kb) ^ (br & 7)) << 4);
                LDM4(rb[jp], bd);
            }
            #pragma unroll
            for (int jp = 0; jp < 4; jp++)
                #pragma unroll
                for (int i = 0; i < 2; i++) {
                    MMAF16(acc[i][jp*2],   ah[i][0], ah[i][1], ah[i][2], ah[i][3], rb[jp][0], rb[jp][1]);
                    MMAF16(acc[i][jp*2+1], ah[i][0], ah[i][1], ah[i][2], ah[i][3], rb[jp][2], rb[jp][3]);
                }
        }

        #pragma unroll
        for (int i = 0; i < 2; i++)
            #pragma unroll
            for (int j = 0; j < 8; j++) {
                mA[i] = fmaxf(mA[i], fmaxf(acc[i][j][0], acc[i][j][1]));
                mB[i] = fmaxf(mB[i], fmaxf(acc[i][j][2], acc[i][j][3]));
            }
    }

    // --- reduce max across lane%4, atomicMax (uint order == float order, >=0) ---
    #pragma unroll
    for (int off = 1; off <= 2; off <<= 1) {
        #pragma unroll
        for (int i = 0; i < 2; i++) {
            mA[i] = fmaxf(mA[i], __shfl_xor_sync(0xffffffff, mA[i], off));
            mB[i] = fmaxf(mB[i], __shfl_xor_sync(0xffffffff, mB[i], off));
        }
    }
    if ((lane & 3) == 0) {
        int r = lane >> 2;
        unsigned int* rm = g_rowmax + nh * LQ + l0;
        #pragma unroll
        for (int i = 0; i < 2; i++) {
            atomicMax(rm + wy * 32 + i * 16 + r,     __float_as_uint(mA[i]));
            atomicMax(rm + wy * 32 + i * 16 + r + 8, __float_as_uint(mB[i]));
        }
    }
}

// ---------------------------------------------------------------------------
// Kernel D: finalize — ksum reduce + mean (phi recomputed fp32) + gate + out.
// grid = 512 blocks; each block = 64 rows of one nh, 4 threads per row.
// ---------------------------------------------------------------------------
__global__ __launch_bounds__(256) void finalize_kernel(
    const float* __restrict__ queries,
    const float* __restrict__ qmask,
    const float* __restrict__ W,
    const float* __restrict__ bias,
    float* __restrict__ out)
{
    const int tid  = threadIdx.x;
    const int r0   = blockIdx.x * 64;         // first global row of this block
    const int nh   = r0 >> 11;
    const int n    = nh >> 3;
    const int h    = nh & 7;

    // --- ksum[nh][64] from per-prep-block partials (32 blocks per nh) ---
    __shared__ float ks_s[64];
    if (tid < 64) {
        const float* kp = g_kpart + (nh << 11) + tid;   // nh*32*64 + d
        float s = 0.f;
        #pragma unroll 8
        for (int b = 0; b < 32; b++) s += kp[b * 64];
        ks_s[tid] = s;
    }
    __syncthreads();

    const int rrow = tid >> 2;                // 0..63 row within block
    const int sub  = tid & 3;                 // quad lane, 16 d's each
    const int grow = r0 + rrow;               // nh*2048 + l
    const int l    = grow & 2047;

    size_t obase = ((((size_t)n * LQ + l) * HH + h) << 6) + sub * 16;
    const float4* qs = (const float4*)(queries + obase);
    float4 v[4];
    v[0] = qs[0]; v[1] = qs[1]; v[2] = qs[2]; v[3] = qs[3];

    // partial mean: phi over this thread's 16 q values (fp32, exact feature map)
    float dot = 0.f;
    #pragma unroll
    for (int j = 0; j < 4; j++) {
        const float* f = (const float*)&v[j];
        const int db = sub * 16 + j * 4;
        dot += phi(f[0]) * ks_s[db];
        dot += phi(f[1]) * ks_s[db + 1];
        dot += phi(f[2]) * ks_s[db + 2];
        dot += phi(f[3]) * ks_s[db + 3];
    }
    dot += __shfl_xor_sync(0xffffffff, dot, 1);
    dot += __shfl_xor_sync(0xffffffff, dot, 2);

    const float qmv = qmask[n * LQ + l];
    float mean = dot * qmv * (1.0f / (float)SK);
    float mx = __uint_as_float(g_rowmax[grow]);
    float lg = fmaf(mean, W[0], fmaf(mx, W[1], bias[0]));
    float gate = 1.0f / (1.0f + __expf(-lg));
    float s = gate * qmv;

    float4* dst = (float4*)(out + obase);
    #pragma unroll
    for (int j = 0; j < 4; j++) {
        float4 w = v[j];
        w.x *= s; w.y *= s; w.z *= s; w.w *= s;
        dst[j] = w;
    }
}

// ---------------------------------------------------------------------------
extern "C" void kernel_launch(void* const* d_in, const int* in_sizes, int n_in,
                              void* d_out, int out_size)
{
    const float* queries = (const float*)d_in[0];
    const float* keys    = (const float*)d_in[1];
    const float* q_mask  = (const float*)d_in[3];
    const float* kv_mask = (const float*)d_in[4];
    const float* W       = (const float*)d_in[5];
    const float* b       = (const float*)d_in[6];
    float* out = (float*)d_out;

    prep_kernel<<<(NHLD / 16) / 256, 256>>>(keys, kv_mask);

    cudaFuncSetAttribute(attn_mma_kernel,
                         cudaFuncAttributeMaxDynamicSharedMemorySize, SMEM_TOTAL);
    dim3 grid(LQ / 128, NHT, ZSPLIT);
    attn_mma_kernel<<<grid, 256, SMEM_TOTAL>>>(queries, q_mask);

    finalize_kernel<<<NROWS / 64, 256>>>(queries, q_mask, W, b, out);
}

// round 12
// speedup vs baseline: 1.0219x; 1.0219x over previous
#include <cuda_runtime.h>
#include <cuda_fp16.h>
#include <math.h>
#include <stdint.h>

#define NB 2
#define LQ 2048
#define SK 2048
#define HH 8
#define DD 64
#define NHT (NB*HH)
#define NHLD (NB*HH*LQ*DD)   // 2,097,152
#define NROWS (NHT*LQ)       // 32768
#define TILES_PER_CTA 16

// Scratch (layout [n][h][row][d]), fp16
__device__ __align__(256) __half g_Qh[NHLD];
__device__ __align__(256) __half g_Kh[NHLD];
__device__ __align__(256) float g_kpart[1024*DD];   // per-prep-block partial K sums
__device__ __align__(256) float g_rowmax[NROWS];

// ---------------------------------------------------------------------------
// PTX helpers
// ---------------------------------------------------------------------------
__device__ __forceinline__ uint32_t smem_u32_of(const void* p) {
    uint32_t a;
    asm("{ .reg .u64 t; cvta.to.shared.u64 t, %1; cvt.u32.u64 %0, t; }" : "=r"(a) : "l"(p));
    return a;
}
#define LDM4(r, addr) \
    asm volatile("ldmatrix.sync.aligned.m8n8.x4.shared.b16 {%0,%1,%2,%3}, [%4];" \
        : "=r"((r)[0]), "=r"((r)[1]), "=r"((r)[2]), "=r"((r)[3]) : "r"(addr))
#define MMAF16(c, a0, a1, a2, a3, b0, b1) \
    asm volatile("mma.sync.aligned.m16n8k16.row.col.f32.f16.f16.f32 " \
        "{%0,%1,%2,%3}, {%4,%5,%6,%7}, {%8,%9}, {%0,%1,%2,%3};" \
        : "+f"((c)[0]), "+f"((c)[1]), "+f"((c)[2]), "+f"((c)[3]) \
        : "r"(a0), "r"(a1), "r"(a2), "r"(a3), "r"(b0), "r"(b1))
#define CPA16(s, g) \
    asm volatile("cp.async.cg.shared.global [%0], [%1], 16;" :: "r"(s), "l"(g))
#define CPC()  asm volatile("cp.async.commit_group;" ::: "memory")
#define CPW1() asm volatile("cp.async.wait_group 1;" ::: "memory")
#define CPW0() asm volatile("cp.async.wait_group 0;" ::: "memory")

// SMEM byte offsets (main kernel)
#define A_OFF 0
#define B_OFF 16384             // + (t%3)*16384, 3 stages
#define RM_OFF 65536            // float[128][2]
#define SMEM_TOTAL 66560

// ---------------------------------------------------------------------------
// Kernel A: feature map + mask + [n,l,h,d]->[n,h,l,d], fp16 out.
// Each block covers 32 rows of one (n,h); reduces its K rows into
// g_kpart[block][64].  (R10-proven form; no rowmax zeroing needed now.)
// ---------------------------------------------------------------------------
__global__ __launch_bounds__(256) void prep_kernel(
    const float* __restrict__ q, const float* __restrict__ k,
    const float* __restrict__ qm, const float* __restrict__ km)
{
    const int tid = threadIdx.x;
    int idx = blockIdx.x * 256 + tid;              // 8-element chunk index

    int e = idx << 3;                              // first element
    int d = e & 63;
    int l = (e >> 6) & 2047;
    int h = (e >> 17) & 7;
    int n = e >> 20;
    size_t src = ((((size_t)n * 2048 + l) * 8 + h) << 6) + d;

    float4 q0 = *(const float4*)(q + src);
    float4 q1 = *(const float4*)(q + src + 4);
    float4 k0 = *(const float4*)(k + src);
    float4 k1 = *(const float4*)(k + src + 4);
    float qmv = qm[n * 2048 + l];
    float kmv = km[n * 2048 + l];

    float fq[8] = {q0.x, q0.y, q0.z, q0.w, q1.x, q1.y, q1.z, q1.w};
    float fk[8] = {k0.x, k0.y, k0.z, k0.w, k1.x, k1.y, k1.z, k1.w};

    float pk[8];
    uint4 oq, ok;
    uint32_t* pqo = (uint32_t*)&oq;
    uint32_t* pko = (uint32_t*)&ok;
    #pragma unroll
    for (int j = 0; j < 4; j++) {
        float ax = ((fq[2*j]   > 0.f) ? (fq[2*j]   + 1.f) : __expf(fq[2*j]))   * qmv;
        float ay = ((fq[2*j+1] > 0.f) ? (fq[2*j+1] + 1.f) : __expf(fq[2*j+1])) * qmv;
        float bx = ((fk[2*j]   > 0.f) ? (fk[2*j]   + 1.f) : __expf(fk[2*j]))   * kmv;
        float by = ((fk[2*j+1] > 0.f) ? (fk[2*j+1] + 1.f) : __expf(fk[2*j+1])) * kmv;
        pk[2*j] = bx; pk[2*j+1] = by;
        __half2 hq = __floats2half2_rn(ax, ay);
        __half2 hk = __floats2half2_rn(bx, by);
        pqo[j] = *(uint32_t*)&hq;
        pko[j] = *(uint32_t*)&hk;
    }
    ((uint4*)g_Qh)[idx] = oq;
    ((uint4*)g_Kh)[idx] = ok;

    // --- block-local K partial sum: 32 rows x 64 d -> 64 floats ---
    __shared__ float stage[32][72];
    const int row = tid >> 3;
    const int dc  = (tid & 7) * 8;
    #pragma unroll
    for (int j = 0; j < 8; j++) stage[row][dc + j] = pk[j];
    __syncthreads();
    if (tid < 64) {
        float s = 0.f;
        #pragma unroll
        for (int r = 0; r < 32; r++) s += stage[r][tid];
        g_kpart[blockIdx.x * 64 + tid] = s;
    }
}

// ---------------------------------------------------------------------------
// Kernel C: fp16 HMMA score GEMM, full S per CTA (ZSPLIT=1).
// grid=(16 ltile, 16 nh), block=256 (8 warps 4x2), 2 CTAs/SM.
// Row max CTA-local -> plain stores, no atomics.
// ---------------------------------------------------------------------------
__global__ void __launch_bounds__(256, 2) attn_mma_kernel()
{
    extern __shared__ char sm[];
    const uint32_t smu = smem_u32_of(sm);
    float* rm = (float*)(sm + RM_OFF);            // [128][2]

    const int tid  = threadIdx.x;
    const int lane = tid & 31;
    const int wid  = tid >> 5;
    const int wx   = wid & 1;       // n-block (64 cols)
    const int wy   = wid >> 1;      // m-block (32 rows)
    const int nh   = blockIdx.y;
    const int l0   = blockIdx.x * 128;

    const int mat    = lane >> 3;
    const int rin    = lane & 7;
    const int a_row  = wy * 32 + (mat & 1) * 8 + rin;
    const int a_kc   = mat >> 1;
    const int b_roff = wx * 64 + (mat >> 1) * 8 + rin;
    const int b_kc   = mat & 1;

    const char* kh_base = (const char*)(g_Kh + (size_t)nh * SK * DD);

    auto issue_b = [&](int t) {
        uint32_t bu = smu + B_OFF + (t % 3) * 16384;
        const char* gk = kh_base + (size_t)t * 128 * DD * 2;
        #pragma unroll
        for (int kk = 0; kk < 4; kk++) {
            int c = tid + kk * 256;
            int row = c >> 3, dc = c & 7;
            uint32_t sw = row * 128 + ((dc ^ (row & 7)) << 4);
            CPA16(bu + sw, gk + c * 16);
        }
    };

    issue_b(0); CPC();
    issue_b(1); CPC();

    // --- A tile (Q fp16, 128 x 64): LDG + swizzled STS (overlaps cp.async) ---
    {
        const char* qh = (const char*)(g_Qh + ((size_t)nh * LQ + l0) * DD);
        #pragma unroll
        for (int c = tid; c < 1024; c += 256) {
            int row = c >> 3, dc = c & 7;
            uint32_t dst = row * 128 + ((dc ^ (row & 7)) << 4);
            *(uint4*)(sm + A_OFF + dst) = *(const uint4*)(qh + c * 16);
        }
    }

    float mA[2] = {0.f, 0.f};
    float mB[2] = {0.f, 0.f};

    for (int t = 0; t < TILES_PER_CTA; t++) {
        if (t + 1 < TILES_PER_CTA) { CPW1(); }
        else                       { CPW0(); }
        __syncthreads();                        // stage t + A visible; t-1 done
        if (t + 2 < TILES_PER_CTA) { issue_b(t + 2); CPC(); }

        const uint32_t Bu = smu + B_OFF + (t % 3) * 16384;
        float acc[2][8][4];
        #pragma unroll
        for (int i = 0; i < 2; i++)
            #pragma unroll
            for (int j = 0; j < 8; j++)
                acc[i][j][0] = acc[i][j][1] = acc[i][j][2] = acc[i][j][3] = 0.f;

        #pragma unroll
        for (int ks = 0; ks < 4; ks++) {
            const int kb = ks * 2;
            uint32_t ah[2][4];
            #pragma unroll
            for (int i = 0; i < 2; i++) {
                int ar = a_row + 16 * i;
                uint32_t ad = smu + A_OFF + ar * 128 + (((a_kc + kb) ^ (ar & 7)) << 4);
                LDM4(ah[i], ad);
            }
            uint32_t rb[4][4];
            #pragma unroll
            for (int jp = 0; jp < 4; jp++) {
                int br = b_roff + jp * 16;
                uint32_t bd = Bu + br * 128 + (((b_kc + kb) ^ (br & 7)) << 4);
                LDM4(rb[jp], bd);
            }
            #pragma unroll
            for (int jp = 0; jp < 4; jp++)
                #pragma unroll
                for (int i = 0; i < 2; i++) {
                    MMAF16(acc[i][jp*2],   ah[i][0], ah[i][1], ah[i][2], ah[i][3], rb[jp][0], rb[jp][1]);
                    MMAF16(acc[i][jp*2+1], ah[i][0], ah[i][1], ah[i][2], ah[i][3], rb[jp][2], rb[jp][3]);
                }
        }

        #pragma unroll
        for (int i = 0; i < 2; i++)
            #pragma unroll
            for (int j = 0; j < 8; j++) {
                mA[i] = fmaxf(mA[i], fmaxf(acc[i][j][0], acc[i][j][1]));
                mB[i] = fmaxf(mB[i], fmaxf(acc[i][j][2], acc[i][j][3]));
            }
    }

    // --- reduce max across lane%4, stage per (row, wx) in smem ---
    #pragma unroll
    for (int off = 1; off <= 2; off <<= 1) {
        #pragma unroll
        for (int i = 0; i < 2; i++) {
            mA[i] = fmaxf(mA[i], __shfl_xor_sync(0xffffffff, mA[i], off));
            mB[i] = fmaxf(mB[i], __shfl_xor_sync(0xffffffff, mB[i], off));
        }
    }
    if ((lane & 3) == 0) {
        int r = lane >> 2;
        #pragma unroll
        for (int i = 0; i < 2; i++) {
            rm[(wy * 32 + i * 16 + r) * 2 + wx]     = mA[i];
            rm[(wy * 32 + i * 16 + r + 8) * 2 + wx] = mB[i];
        }
    }
    __syncthreads();
    if (tid < 128)
        g_rowmax[nh * LQ + l0 + tid] = fmaxf(rm[tid * 2], rm[tid * 2 + 1]);
}

// ---------------------------------------------------------------------------
// Kernel D: finalize — ksum reduce + mean + gate + output.
// grid = 512 blocks; each block = 64 rows of one nh, 4 threads per row.
// ---------------------------------------------------------------------------
__global__ __launch_bounds__(256) void finalize_kernel(
    const float* __restrict__ queries,
    const float* __restrict__ qmask,
    const float* __restrict__ W,
    const float* __restrict__ bias,
    float* __restrict__ out)
{
    const int tid  = threadIdx.x;
    const int r0   = blockIdx.x * 64;         // first global row of this block
    const int nh   = r0 >> 11;
    const int n    = nh >> 3;
    const int h    = nh & 7;

    // --- ksum[nh][64] from per-prep-block partials (64 blocks per nh) ---
    __shared__ float ks_s[64];
    if (tid < 64) {
        const float* kp = g_kpart + (nh << 12) + tid;   // nh*64*64 + d
        float s = 0.f;
        #pragma unroll 16
        for (int b = 0; b < 64; b++) s += kp[b * 64];
        ks_s[tid] = s;
    }
    __syncthreads();

    const int rrow = tid >> 2;                // 0..63 row within block
    const int sub  = tid & 3;                 // quad lane
    const int grow = r0 + rrow;               // nh*2048 + l
    const int l    = grow & 2047;

    // partial mean: 16 d's per thread = 2x uint4 of fp16
    float mean = 0.f;
    {
        const uint4* ph = (const uint4*)(g_Qh + (size_t)grow * DD) + sub * 2;
        #pragma unroll
        for (int c = 0; c < 2; c++) {
            uint4 v = ph[c];
            const uint32_t* w32 = (const uint32_t*)&v;
            const int db = sub * 16 + c * 8;
            #pragma unroll
            for (int w = 0; w < 4; w++) {
                float2 f = __half22float2(*(const __half2*)&w32[w]);
                mean += f.x * ks_s[db + w * 2];
                mean += f.y * ks_s[db + w * 2 + 1];
            }
        }
    }
    mean += __shfl_xor_sync(0xffffffff, mean, 1);
    mean += __shfl_xor_sync(0xffffffff, mean, 2);
    mean *= (1.0f / (float)SK);

    float mx = g_rowmax[grow];
    float lg = fmaf(mean, W[0], fmaf(mx, W[1], bias[0]));
    float gate = 1.0f / (1.0f + __expf(-lg));
    float s = gate * qmask[n * LQ + l];

    size_t obase = ((((size_t)n * LQ + l) * HH + h) << 6) + sub * 16;
    const float4* qs = (const float4*)(queries + obase);
    float4* dst = (float4*)(out + obase);
    #pragma unroll
    for (int j = 0; j < 4; j++) {
        float4 v = qs[j];
        v.x *= s; v.y *= s; v.z *= s; v.w *= s;
        dst[j] = v;
    }
}

// ---------------------------------------------------------------------------
extern "C" void kernel_launch(void* const* d_in, const int* in_sizes, int n_in,
                              void* d_out, int out_size)
{
    const float* queries = (const float*)d_in[0];
    const float* keys    = (const float*)d_in[1];
    const float* q_mask  = (const float*)d_in[3];
    const float* kv_mask = (const float*)d_in[4];
    const float* W       = (const float*)d_in[5];
    const float* b       = (const float*)d_in[6];
    float* out = (float*)d_out;

    prep_kernel<<<(NHLD / 8) / 256, 256>>>(queries, keys, q_mask, kv_mask);

    cudaFuncSetAttribute(attn_mma_kernel,
                         cudaFuncAttributeMaxDynamicSharedMemorySize, SMEM_TOTAL);
    dim3 grid(LQ / 128, NHT);
    attn_mma_kernel<<<grid, 256, SMEM_TOTAL>>>();

    finalize_kernel<<<NROWS / 64, 256>>>(queries, q_mask, W, b, out);
}

// round 13
// speedup vs baseline: 1.0697x; 1.0468x over previous
#include <cuda_runtime.h>
#include <cuda_fp16.h>
#include <math.h>
#include <stdint.h>

#define NB 2
#define LQ 2048
#define SK 2048
#define HH 8
#define DD 64
#define NHT (NB*HH)
#define NHLD (NB*HH*LQ*DD)   // 2,097,152
#define NROWS (NHT*LQ)       // 32768
#define ZSPLIT 2
#define TILES_PER_CTA 8      // 8 tiles x 128 s = 1024 s per CTA

// Scratch (layout [n][h][row][d]), fp16
__device__ __align__(256) __half g_Qh[NHLD];
__device__ __align__(256) __half g_Kh[NHLD];
__device__ __align__(256) float g_kpart[1024*DD];   // per-prep-block partial K sums
__device__ __align__(256) float g_rowmax[ZSPLIT*NROWS];

// ---------------------------------------------------------------------------
// PTX helpers
// ---------------------------------------------------------------------------
__device__ __forceinline__ uint32_t smem_u32_of(const void* p) {
    uint32_t a;
    asm("{ .reg .u64 t; cvta.to.shared.u64 t, %1; cvt.u32.u64 %0, t; }" : "=r"(a) : "l"(p));
    return a;
}
#define LDM4(r, addr) \
    asm volatile("ldmatrix.sync.aligned.m8n8.x4.shared.b16 {%0,%1,%2,%3}, [%4];" \
        : "=r"((r)[0]), "=r"((r)[1]), "=r"((r)[2]), "=r"((r)[3]) : "r"(addr))
#define MMAF16(c, a0, a1, a2, a3, b0, b1) \
    asm volatile("mma.sync.aligned.m16n8k16.row.col.f32.f16.f16.f32 " \
        "{%0,%1,%2,%3}, {%4,%5,%6,%7}, {%8,%9}, {%0,%1,%2,%3};" \
        : "+f"((c)[0]), "+f"((c)[1]), "+f"((c)[2]), "+f"((c)[3]) \
        : "r"(a0), "r"(a1), "r"(a2), "r"(a3), "r"(b0), "r"(b1))
#define CPA16(s, g) \
    asm volatile("cp.async.cg.shared.global [%0], [%1], 16;" :: "r"(s), "l"(g))
#define CPC()  asm volatile("cp.async.commit_group;" ::: "memory")
#define CPW1() asm volatile("cp.async.wait_group 1;" ::: "memory")
#define CPW0() asm volatile("cp.async.wait_group 0;" ::: "memory")

// SMEM: 3 group-slots x 2 tiles x 16KB = 96KB. A staged in slot2 pre-loop.
// rowmax staging overlays slot0 post-loop.
#define A_STAGE 65536
#define SMEM_TOTAL 98304
__device__ __forceinline__ uint32_t b_slot(int t) {
    return (uint32_t)(((t >> 1) % 3) * 32768 + (t & 1) * 16384);
}

// ---------------------------------------------------------------------------
// Kernel A: feature map + mask + [n,l,h,d]->[n,h,l,d], fp16 out.
// Each block covers 32 rows of one (n,h); reduces its K rows into
// g_kpart[block][64].
// ---------------------------------------------------------------------------
__global__ __launch_bounds__(256) void prep_kernel(
    const float* __restrict__ q, const float* __restrict__ k,
    const float* __restrict__ qm, const float* __restrict__ km)
{
    const int tid = threadIdx.x;
    int idx = blockIdx.x * 256 + tid;              // 8-element chunk index

    int e = idx << 3;
    int d = e & 63;
    int l = (e >> 6) & 2047;
    int h = (e >> 17) & 7;
    int n = e >> 20;
    size_t src = ((((size_t)n * 2048 + l) * 8 + h) << 6) + d;

    float4 q0 = *(const float4*)(q + src);
    float4 q1 = *(const float4*)(q + src + 4);
    float4 k0 = *(const float4*)(k + src);
    float4 k1 = *(const float4*)(k + src + 4);
    float qmv = qm[n * 2048 + l];
    float kmv = km[n * 2048 + l];

    float fq[8] = {q0.x, q0.y, q0.z, q0.w, q1.x, q1.y, q1.z, q1.w};
    float fk[8] = {k0.x, k0.y, k0.z, k0.w, k1.x, k1.y, k1.z, k1.w};

    float pk[8];
    uint4 oq, ok;
    uint32_t* pqo = (uint32_t*)&oq;
    uint32_t* pko = (uint32_t*)&ok;
    #pragma unroll
    for (int j = 0; j < 4; j++) {
        float ax = ((fq[2*j]   > 0.f) ? (fq[2*j]   + 1.f) : __expf(fq[2*j]))   * qmv;
        float ay = ((fq[2*j+1] > 0.f) ? (fq[2*j+1] + 1.f) : __expf(fq[2*j+1])) * qmv;
        float bx = ((fk[2*j]   > 0.f) ? (fk[2*j]   + 1.f) : __expf(fk[2*j]))   * kmv;
        float by = ((fk[2*j+1] > 0.f) ? (fk[2*j+1] + 1.f) : __expf(fk[2*j+1])) * kmv;
        pk[2*j] = bx; pk[2*j+1] = by;
        __half2 hq = __floats2half2_rn(ax, ay);
        __half2 hk = __floats2half2_rn(bx, by);
        pqo[j] = *(uint32_t*)&hq;
        pko[j] = *(uint32_t*)&hk;
    }
    ((uint4*)g_Qh)[idx] = oq;
    ((uint4*)g_Kh)[idx] = ok;

    __shared__ float stage[32][72];
    const int row = tid >> 3;
    const int dc  = (tid & 7) * 8;
    #pragma unroll
    for (int j = 0; j < 8; j++) stage[row][dc + j] = pk[j];
    __syncthreads();
    if (tid < 64) {
        float s = 0.f;
        #pragma unroll
        for (int r = 0; r < 32; r++) s += stage[r][tid];
        g_kpart[blockIdx.x * 64 + tid] = s;
    }
}

// ---------------------------------------------------------------------------
// Kernel C: fp16 HMMA score GEMM. A fragments register-resident; B in a
// 3-slot / 2-tile-group cp.async ring (1 sync per 2 tiles).
// grid=(16 ltile, 16 nh, 2 z), block=256 (8 warps 4x2), 2 CTAs/SM.
// Per-z rowmax written with plain stores to g_rowmax[z].
// ---------------------------------------------------------------------------
__global__ void __launch_bounds__(256, 2) attn_mma_kernel()
{
    extern __shared__ char sm[];
    const uint32_t smu = smem_u32_of(sm);

    const int tid  = threadIdx.x;
    const int lane = tid & 31;
    const int wid  = tid >> 5;
    const int wx   = wid & 1;       // n-block (64 cols)
    const int wy   = wid >> 1;      // m-block (32 rows)
    const int nh   = blockIdx.y;
    const int l0   = blockIdx.x * 128;
    const int ts0  = blockIdx.z * TILES_PER_CTA;

    const int mat    = lane >> 3;
    const int rin    = lane & 7;
    const int a_row  = wy * 32 + (mat & 1) * 8 + rin;
    const int a_kc   = mat >> 1;
    const int b_roff = wx * 64 + (mat >> 1) * 8 + rin;
    const int b_kc   = mat & 1;

    const char* kh_base = (const char*)(g_Kh + (size_t)nh * SK * DD);

    auto issue_b = [&](int t) {
        uint32_t bu = smu + b_slot(t);
        const char* gk = kh_base + (size_t)(ts0 + t) * 128 * DD * 2;
        #pragma unroll
        for (int kk = 0; kk < 4; kk++) {
            int c = tid + kk * 256;
            int row = c >> 3, dc = c & 7;
            uint32_t sw = row * 128 + ((dc ^ (row & 7)) << 4);
            CPA16(bu + sw, gk + c * 16);
        }
    };

    // prologue: issue groups 0 (t0,t1) and 1 (t2,t3)
    issue_b(0); issue_b(1); CPC();
    issue_b(2); issue_b(3); CPC();

    // stage A (Q tile) in slot2, then hoist fragments to registers
    {
        const char* qh = (const char*)(g_Qh + ((size_t)nh * LQ + l0) * DD);
        #pragma unroll
        for (int c = tid; c < 1024; c += 256) {
            int row = c >> 3, dc = c & 7;
            uint32_t dst = row * 128 + ((dc ^ (row & 7)) << 4);
            *(uint4*)(sm + A_STAGE + dst) = *(const uint4*)(qh + c * 16);
        }
    }
    __syncthreads();

    uint32_t ah[4][2][4];               // [ks][i][frag] — 32 regs
    #pragma unroll
    for (int ks = 0; ks < 4; ks++)
        #pragma unroll
        for (int i = 0; i < 2; i++) {
            int ar = a_row + 16 * i;
            uint32_t ad = smu + A_STAGE + ar * 128 + (((a_kc + ks * 2) ^ (ar & 7)) << 4);
            LDM4(ah[ks][i], ad);
        }

    float mA[2] = {0.f, 0.f};
    float mB[2] = {0.f, 0.f};

    for (int g = 0; g < TILES_PER_CTA / 2; g++) {
        if (g < 3) { CPW1(); }
        else       { CPW0(); }
        __syncthreads();   // group g visible; group g-1 compute done (+A ldm done at g=0)
        if (g + 2 < TILES_PER_CTA / 2) { issue_b(2*(g+2)); issue_b(2*(g+2)+1); CPC(); }

        #pragma unroll
        for (int tt = 0; tt < 2; tt++) {
            const int t = g * 2 + tt;
            const uint32_t Bu = smu + b_slot(t);

            float acc[2][8][4];
            #pragma unroll
            for (int i = 0; i < 2; i++)
                #pragma unroll
                for (int j = 0; j < 8; j++)
                    acc[i][j][0] = acc[i][j][1] = acc[i][j][2] = acc[i][j][3] = 0.f;

            #pragma unroll
            for (int ks = 0; ks < 4; ks++) {
                const int kb = ks * 2;
                #pragma unroll
                for (int jp = 0; jp < 4; jp++) {
                    int br = b_roff + jp * 16;
                    uint32_t bd = Bu + br * 128 + (((b_kc + kb) ^ (br & 7)) << 4);
                    uint32_t rb[4];
                    LDM4(rb, bd);
                    #pragma unroll
                    for (int i = 0; i < 2; i++) {
                        MMAF16(acc[i][jp*2],   ah[ks][i][0], ah[ks][i][1], ah[ks][i][2], ah[ks][i][3], rb[0], rb[1]);
                        MMAF16(acc[i][jp*2+1], ah[ks][i][0], ah[ks][i][1], ah[ks][i][2], ah[ks][i][3], rb[2], rb[3]);
                    }
                }
            }

            #pragma unroll
            for (int i = 0; i < 2; i++)
                #pragma unroll
                for (int j = 0; j < 8; j++) {
                    mA[i] = fmaxf(mA[i], fmaxf(acc[i][j][0], acc[i][j][1]));
                    mB[i] = fmaxf(mB[i], fmaxf(acc[i][j][2], acc[i][j][3]));
                }
        }
    }

    // --- reduce max across lane%4; stage in smem (overlay slot0, done) ---
    #pragma unroll
    for (int off = 1; off <= 2; off <<= 1) {
        #pragma unroll
        for (int i = 0; i < 2; i++) {
            mA[i] = fmaxf(mA[i], __shfl_xor_sync(0xffffffff, mA[i], off));
            mB[i] = fmaxf(mB[i], __shfl_xor_sync(0xffffffff, mB[i], off));
        }
    }
    __syncthreads();                    // all compute done; slot0 reusable
    float* rm = (float*)sm;             // [128][2]
    if ((lane & 3) == 0) {
        int r = lane >> 2;
        #pragma unroll
        for (int i = 0; i < 2; i++) {
            rm[(wy * 32 + i * 16 + r) * 2 + wx]     = mA[i];
            rm[(wy * 32 + i * 16 + r + 8) * 2 + wx] = mB[i];
        }
    }
    __syncthreads();
    if (tid < 128)
        g_rowmax[blockIdx.z * NROWS + nh * LQ + l0 + tid] = fmaxf(rm[tid * 2], rm[tid * 2 + 1]);
}

// ---------------------------------------------------------------------------
// Kernel D: finalize — ksum reduce + mean + gate + output.
// grid = 512 blocks; each block = 64 rows of one nh, 4 threads per row.
// ---------------------------------------------------------------------------
__global__ __launch_bounds__(256) void finalize_kernel(
    const float* __restrict__ queries,
    const float* __restrict__ qmask,
    const float* __restrict__ W,
    const float* __restrict__ bias,
    float* __restrict__ out)
{
    const int tid  = threadIdx.x;
    const int r0   = blockIdx.x * 64;
    const int nh   = r0 >> 11;
    const int n    = nh >> 3;
    const int h    = nh & 7;

    __shared__ float ks_s[64];
    if (tid < 64) {
        const float* kp = g_kpart + (nh << 12) + tid;   // nh*64*64 + d
        float s = 0.f;
        #pragma unroll 16
        for (int b = 0; b < 64; b++) s += kp[b * 64];
        ks_s[tid] = s;
    }
    __syncthreads();

    const int rrow = tid >> 2;
    const int sub  = tid & 3;
    const int grow = r0 + rrow;
    const int l    = grow & 2047;

    float mean = 0.f;
    {
        const uint4* ph = (const uint4*)(g_Qh + (size_t)grow * DD) + sub * 2;
        #pragma unroll
        for (int c = 0; c < 2; c++) {
            uint4 v = ph[c];
            const uint32_t* w32 = (const uint32_t*)&v;
            const int db = sub * 16 + c * 8;
            #pragma unroll
            for (int w = 0; w < 4; w++) {
                float2 f = __half22float2(*(const __half2*)&w32[w]);
                mean += f.x * ks_s[db + w * 2];
                mean += f.y * ks_s[db + w * 2 + 1];
            }
        }
    }
    mean += __shfl_xor_sync(0xffffffff, mean, 1);
    mean += __shfl_xor_sync(0xffffffff, mean, 2);
    mean *= (1.0f / (float)SK);

    float mx = fmaxf(g_rowmax[grow], g_rowmax[NROWS + grow]);
    float lg = fmaf(mean, W[0], fmaf(mx, W[1], bias[0]));
    float gate = 1.0f / (1.0f + __expf(-lg));
    float s = gate * qmask[n * LQ + l];

    size_t obase = ((((size_t)n * LQ + l) * HH + h) << 6) + sub * 16;
    const float4* qs = (const float4*)(queries + obase);
    float4* dst = (float4*)(out + obase);
    #pragma unroll
    for (int j = 0; j < 4; j++) {
        float4 v = qs[j];
        v.x *= s; v.y *= s; v.z *= s; v.w *= s;
        dst[j] = v;
    }
}

// ---------------------------------------------------------------------------
extern "C" void kernel_launch(void* const* d_in, const int* in_sizes, int n_in,
                              void* d_out, int out_size)
{
    const float* queries = (const float*)d_in[0];
    const float* keys    = (const float*)d_in[1];
    const float* q_mask  = (const float*)d_in[3];
    const float* kv_mask = (const float*)d_in[4];
    const float* W       = (const float*)d_in[5];
    const float* b       = (const float*)d_in[6];
    float* out = (float*)d_out;

    prep_kernel<<<(NHLD / 8) / 256, 256>>>(queries, keys, q_mask, kv_mask);

    cudaFuncSetAttribute(attn_mma_kernel,
                         cudaFuncAttributeMaxDynamicSharedMemorySize, SMEM_TOTAL);
    dim3 grid(LQ / 128, NHT, ZSPLIT);
    attn_mma_kernel<<<grid, 256, SMEM_TOTAL>>>();

    finalize_kernel<<<NROWS / 64, 256>>>(queries, q_mask, W, b, out);
}

// round 14
// speedup vs baseline: 1.0706x; 1.0009x over previous
#include <cuda_runtime.h>
#include <cuda_fp16.h>
#include <math.h>
#include <stdint.h>

#define NB 2
#define LQ 2048
#define SK 2048
#define HH 8
#define DD 64
#define NHT (NB*HH)
#define NHLD (NB*HH*LQ*DD)   // 2,097,152
#define NROWS (NHT*LQ)       // 32768
#define ZSPLIT 2
#define TILES_PER_CTA 8      // 8 tiles x 128 s = 1024 s per CTA

// Scratch (layout [n][h][row][d]), fp16
__device__ __align__(256) __half g_Qh[NHLD];
__device__ __align__(256) __half g_Kh[NHLD];
__device__ __align__(256) float g_kpart[1024*DD];   // per-prep-block partial K sums
__device__ __align__(256) float g_rowmax[ZSPLIT*NROWS];

// ---------------------------------------------------------------------------
// PTX helpers
// ---------------------------------------------------------------------------
__device__ __forceinline__ uint32_t smem_u32_of(const void* p) {
    uint32_t a;
    asm("{ .reg .u64 t; cvta.to.shared.u64 t, %1; cvt.u32.u64 %0, t; }" : "=r"(a) : "l"(p));
    return a;
}
#define LDM4(r, addr) \
    asm volatile("ldmatrix.sync.aligned.m8n8.x4.shared.b16 {%0,%1,%2,%3}, [%4];" \
        : "=r"((r)[0]), "=r"((r)[1]), "=r"((r)[2]), "=r"((r)[3]) : "r"(addr))
#define MMAF16(c, a0, a1, a2, a3, b0, b1) \
    asm volatile("mma.sync.aligned.m16n8k16.row.col.f32.f16.f16.f32 " \
        "{%0,%1,%2,%3}, {%4,%5,%6,%7}, {%8,%9}, {%0,%1,%2,%3};" \
        : "+f"((c)[0]), "+f"((c)[1]), "+f"((c)[2]), "+f"((c)[3]) \
        : "r"(a0), "r"(a1), "r"(a2), "r"(a3), "r"(b0), "r"(b1))
#define CPA16(s, g) \
    asm volatile("cp.async.cg.shared.global [%0], [%1], 16;" :: "r"(s), "l"(g))
#define CPC()  asm volatile("cp.async.commit_group;" ::: "memory")
#define CPW1() asm volatile("cp.async.wait_group 1;" ::: "memory")
#define CPW0() asm volatile("cp.async.wait_group 0;" ::: "memory")

__device__ __forceinline__ float phi32(float x) {
    return (x > 0.f) ? (x + 1.f) : __expf(x);
}

// SMEM: 3 group-slots x 2 tiles x 16KB = 96KB. A staged in slot2 pre-loop.
#define A_STAGE 65536
#define SMEM_TOTAL 98304
__device__ __forceinline__ uint32_t b_slot(int t) {
    return (uint32_t)(((t >> 1) % 3) * 32768 + (t & 1) * 16384);
}

// ---------------------------------------------------------------------------
// Kernel A: feature map (fp16x2 h2exp path) + mask + [n,l,h,d]->[n,h,l,d].
// Each block covers 32 rows of one (n,h); reduces its K rows into
// g_kpart[block][64].
// ---------------------------------------------------------------------------
__global__ __launch_bounds__(256) void prep_kernel(
    const float* __restrict__ q, const float* __restrict__ k,
    const float* __restrict__ qm, const float* __restrict__ km)
{
    const int tid = threadIdx.x;
    int idx = blockIdx.x * 256 + tid;              // 8-element chunk index

    int e = idx << 3;
    int d = e & 63;
    int l = (e >> 6) & 2047;
    int h = (e >> 17) & 7;
    int n = e >> 20;
    size_t src = ((((size_t)n * 2048 + l) * 8 + h) << 6) + d;

    float4 q0 = *(const float4*)(q + src);
    float4 q1 = *(const float4*)(q + src + 4);
    float4 k0 = *(const float4*)(k + src);
    float4 k1 = *(const float4*)(k + src + 4);
    const __half2 qm2 = __float2half2_rn(qm[n * 2048 + l]);
    const __half2 km2 = __float2half2_rn(km[n * 2048 + l]);
    const __half2 one2  = __float2half2_rn(1.0f);
    const __half2 zero2 = __float2half2_rn(0.0f);

    float fq[8] = {q0.x, q0.y, q0.z, q0.w, q1.x, q1.y, q1.z, q1.w};
    float fk[8] = {k0.x, k0.y, k0.z, k0.w, k1.x, k1.y, k1.z, k1.w};

    float pk[8];
    uint4 oq, ok;
    uint32_t* pqo = (uint32_t*)&oq;
    uint32_t* pko = (uint32_t*)&ok;
    #pragma unroll
    for (int j = 0; j < 4; j++) {
        __half2 hq = __floats2half2_rn(fq[2*j], fq[2*j+1]);
        __half2 hk = __floats2half2_rn(fk[2*j], fk[2*j+1]);
        // phi = x>0 ? x+1 : exp(x), computed as ex + m*( (x+1) - ex )
        __half2 eq = h2exp(hq);
        __half2 ek = h2exp(hk);
        __half2 mq = __hgt2(hq, zero2);            // 1.0 where x>0
        __half2 mk = __hgt2(hk, zero2);
        __half2 rq = __hfma2(mq, __hsub2(__hadd2(hq, one2), eq), eq);
        __half2 rk = __hfma2(mk, __hsub2(__hadd2(hk, one2), ek), ek);
        rq = __hmul2(rq, qm2);
        rk = __hmul2(rk, km2);
        pqo[j] = *(uint32_t*)&rq;
        pko[j] = *(uint32_t*)&rk;
        float2 fk2 = __half22float2(rk);
        pk[2*j]   = fk2.x;
        pk[2*j+1] = fk2.y;
    }
    ((uint4*)g_Qh)[idx] = oq;
    ((uint4*)g_Kh)[idx] = ok;

    // --- block-local K partial sum: 32 rows x 64 d -> 64 floats ---
    __shared__ float stage[32][72];
    const int row = tid >> 3;
    const int dc  = (tid & 7) * 8;
    #pragma unroll
    for (int j = 0; j < 8; j++) stage[row][dc + j] = pk[j];
    __syncthreads();
    if (tid < 64) {
        float s = 0.f;
        #pragma unroll
        for (int r = 0; r < 32; r++) s += stage[r][tid];
        g_kpart[blockIdx.x * 64 + tid] = s;
    }
}

// ---------------------------------------------------------------------------
// Kernel C: fp16 HMMA score GEMM. A fragments register-resident; B in a
// 3-slot / 2-tile-group cp.async ring.  (Frozen R13 form.)
// grid=(16 ltile, 16 nh, 2 z), block=256 (8 warps 4x2), 2 CTAs/SM.
// ---------------------------------------------------------------------------
__global__ void __launch_bounds__(256, 2) attn_mma_kernel()
{
    extern __shared__ char sm[];
    const uint32_t smu = smem_u32_of(sm);

    const int tid  = threadIdx.x;
    const int lane = tid & 31;
    const int wid  = tid >> 5;
    const int wx   = wid & 1;
    const int wy   = wid >> 1;
    const int nh   = blockIdx.y;
    const int l0   = blockIdx.x * 128;
    const int ts0  = blockIdx.z * TILES_PER_CTA;

    const int mat    = lane >> 3;
    const int rin    = lane & 7;
    const int a_row  = wy * 32 + (mat & 1) * 8 + rin;
    const int a_kc   = mat >> 1;
    const int b_roff = wx * 64 + (mat >> 1) * 8 + rin;
    const int b_kc   = mat & 1;

    const char* kh_base = (const char*)(g_Kh + (size_t)nh * SK * DD);

    auto issue_b = [&](int t) {
        uint32_t bu = smu + b_slot(t);
        const char* gk = kh_base + (size_t)(ts0 + t) * 128 * DD * 2;
        #pragma unroll
        for (int kk = 0; kk < 4; kk++) {
            int c = tid + kk * 256;
            int row = c >> 3, dc = c & 7;
            uint32_t sw = row * 128 + ((dc ^ (row & 7)) << 4);
            CPA16(bu + sw, gk + c * 16);
        }
    };

    issue_b(0); issue_b(1); CPC();
    issue_b(2); issue_b(3); CPC();

    {
        const char* qh = (const char*)(g_Qh + ((size_t)nh * LQ + l0) * DD);
        #pragma unroll
        for (int c = tid; c < 1024; c += 256) {
            int row = c >> 3, dc = c & 7;
            uint32_t dst = row * 128 + ((dc ^ (row & 7)) << 4);
            *(uint4*)(sm + A_STAGE + dst) = *(const uint4*)(qh + c * 16);
        }
    }
    __syncthreads();

    uint32_t ah[4][2][4];               // [ks][i][frag]
    #pragma unroll
    for (int ks = 0; ks < 4; ks++)
        #pragma unroll
        for (int i = 0; i < 2; i++) {
            int ar = a_row + 16 * i;
            uint32_t ad = smu + A_STAGE + ar * 128 + (((a_kc + ks * 2) ^ (ar & 7)) << 4);
            LDM4(ah[ks][i], ad);
        }

    float mA[2] = {0.f, 0.f};
    float mB[2] = {0.f, 0.f};

    for (int g = 0; g < TILES_PER_CTA / 2; g++) {
        if (g < 3) { CPW1(); }
        else       { CPW0(); }
        __syncthreads();
        if (g + 2 < TILES_PER_CTA / 2) { issue_b(2*(g+2)); issue_b(2*(g+2)+1); CPC(); }

        #pragma unroll
        for (int tt = 0; tt < 2; tt++) {
            const int t = g * 2 + tt;
            const uint32_t Bu = smu + b_slot(t);

            float acc[2][8][4];
            #pragma unroll
            for (int i = 0; i < 2; i++)
                #pragma unroll
                for (int j = 0; j < 8; j++)
                    acc[i][j][0] = acc[i][j][1] = acc[i][j][2] = acc[i][j][3] = 0.f;

            #pragma unroll
            for (int ks = 0; ks < 4; ks++) {
                const int kb = ks * 2;
                #pragma unroll
                for (int jp = 0; jp < 4; jp++) {
                    int br = b_roff + jp * 16;
                    uint32_t bd = Bu + br * 128 + (((b_kc + kb) ^ (br & 7)) << 4);
                    uint32_t rb[4];
                    LDM4(rb, bd);
                    #pragma unroll
                    for (int i = 0; i < 2; i++) {
                        MMAF16(acc[i][jp*2],   ah[ks][i][0], ah[ks][i][1], ah[ks][i][2], ah[ks][i][3], rb[0], rb[1]);
                        MMAF16(acc[i][jp*2+1], ah[ks][i][0], ah[ks][i][1], ah[ks][i][2], ah[ks][i][3], rb[2], rb[3]);
                    }
                }
            }

            #pragma unroll
            for (int i = 0; i < 2; i++)
                #pragma unroll
                for (int j = 0; j < 8; j++) {
                    mA[i] = fmaxf(mA[i], fmaxf(acc[i][j][0], acc[i][j][1]));
                    mB[i] = fmaxf(mB[i], fmaxf(acc[i][j][2], acc[i][j][3]));
                }
        }
    }

    #pragma unroll
    for (int off = 1; off <= 2; off <<= 1) {
        #pragma unroll
        for (int i = 0; i < 2; i++) {
            mA[i] = fmaxf(mA[i], __shfl_xor_sync(0xffffffff, mA[i], off));
            mB[i] = fmaxf(mB[i], __shfl_xor_sync(0xffffffff, mB[i], off));
        }
    }
    __syncthreads();
    float* rm = (float*)sm;
    if ((lane & 3) == 0) {
        int r = lane >> 2;
        #pragma unroll
        for (int i = 0; i < 2; i++) {
            rm[(wy * 32 + i * 16 + r) * 2 + wx]     = mA[i];
            rm[(wy * 32 + i * 16 + r + 8) * 2 + wx] = mB[i];
        }
    }
    __syncthreads();
    if (tid < 128)
        g_rowmax[blockIdx.z * NROWS + nh * LQ + l0 + tid] = fmaxf(rm[tid * 2], rm[tid * 2 + 1]);
}

// ---------------------------------------------------------------------------
// Kernel D: finalize — ksum reduce + mean (phi recomputed fp32 from queries,
// no g_Qh read) + gate + output.  512 blocks, 4 threads per row.
// ---------------------------------------------------------------------------
__global__ __launch_bounds__(256) void finalize_kernel(
    const float* __restrict__ queries,
    const float* __restrict__ qmask,
    const float* __restrict__ W,
    const float* __restrict__ bias,
    float* __restrict__ out)
{
    const int tid  = threadIdx.x;
    const int r0   = blockIdx.x * 64;
    const int nh   = r0 >> 11;
    const int n    = nh >> 3;
    const int h    = nh & 7;

    __shared__ float ks_s[64];
    if (tid < 64) {
        const float* kp = g_kpart + (nh << 12) + tid;   // nh*64*64 + d
        float s = 0.f;
        #pragma unroll 16
        for (int b = 0; b < 64; b++) s += kp[b * 64];
        ks_s[tid] = s;
    }
    __syncthreads();

    const int rrow = tid >> 2;
    const int sub  = tid & 3;
    const int grow = r0 + rrow;
    const int l    = grow & 2047;

    size_t obase = ((((size_t)n * LQ + l) * HH + h) << 6) + sub * 16;
    const float4* qs = (const float4*)(queries + obase);
    float4 v[4];
    v[0] = qs[0]; v[1] = qs[1]; v[2] = qs[2]; v[3] = qs[3];

    // partial mean: phi over this thread's 16 q values (fp32 exact feature map)
    float dot = 0.f;
    #pragma unroll
    for (int j = 0; j < 4; j++) {
        const float* f = (const float*)&v[j];
        const int db = sub * 16 + j * 4;
        dot += phi32(f[0]) * ks_s[db];
        dot += phi32(f[1]) * ks_s[db + 1];
        dot += phi32(f[2]) * ks_s[db + 2];
        dot += phi32(f[3]) * ks_s[db + 3];
    }
    dot += __shfl_xor_sync(0xffffffff, dot, 1);
    dot += __shfl_xor_sync(0xffffffff, dot, 2);

    const float qmv = qmask[n * LQ + l];
    float mean = dot * qmv * (1.0f / (float)SK);
    float mx = fmaxf(g_rowmax[grow], g_rowmax[NROWS + grow]);
    float lg = fmaf(mean, W[0], fmaf(mx, W[1], bias[0]));
    float gate = 1.0f / (1.0f + __expf(-lg));
    float s = gate * qmv;

    float4* dst = (float4*)(out + obase);
    #pragma unroll
    for (int j = 0; j < 4; j++) {
        float4 w = v[j];
        w.x *= s; w.y *= s; w.z *= s; w.w *= s;
        dst[j] = w;
    }
}

// ---------------------------------------------------------------------------
extern "C" void kernel_launch(void* const* d_in, const int* in_sizes, int n_in,
                              void* d_out, int out_size)
{
    const float* queries = (const float*)d_in[0];
    const float* keys    = (const float*)d_in[1];
    const float* q_mask  = (const float*)d_in[3];
    const float* kv_mask = (const float*)d_in[4];
    const float* W       = (const float*)d_in[5];
    const float* b       = (const float*)d_in[6];
    float* out = (float*)d_out;

    prep_kernel<<<(NHLD / 8) / 256, 256>>>(queries, keys, q_mask, kv_mask);

    cudaFuncSetAttribute(attn_mma_kernel,
                         cudaFuncAttributeMaxDynamicSharedMemorySize, SMEM_TOTAL);
    dim3 grid(LQ / 128, NHT, ZSPLIT);
    attn_mma_kernel<<<grid, 256, SMEM_TOTAL>>>();

    finalize_kernel<<<NROWS / 64, 256>>>(queries, q_mask, W, b, out);
}

// round 15
// speedup vs baseline: 1.0958x; 1.0235x over previous
#include <cuda_runtime.h>
#include <cuda_fp16.h>
#include <math.h>
#include <stdint.h>

#define NB 2
#define LQ 2048
#define SK 2048
#define HH 8
#define DD 64
#define NHT (NB*HH)
#define NHLD (NB*HH*LQ*DD)   // 2,097,152
#define NROWS (NHT*LQ)       // 32768
#define NCTA 296             // 2 CTAs/SM x 148 SMs, one wave
#define NUNITS 4096          // 256 groups x 16 tiles

// Scratch (layout [n][h][row][d]), fp16
__device__ __align__(256) __half g_Qh[NHLD];
__device__ __align__(256) __half g_Kh[NHLD];
__device__ __align__(256) float g_kpart[1024*DD];   // per-prep-block partial K sums
__device__ __align__(256) unsigned int g_rowmax[NROWS];

// ---------------------------------------------------------------------------
// PTX helpers
// ---------------------------------------------------------------------------
__device__ __forceinline__ uint32_t smem_u32_of(const void* p) {
    uint32_t a;
    asm("{ .reg .u64 t; cvta.to.shared.u64 t, %1; cvt.u32.u64 %0, t; }" : "=r"(a) : "l"(p));
    return a;
}
#define LDM4(r, addr) \
    asm volatile("ldmatrix.sync.aligned.m8n8.x4.shared.b16 {%0,%1,%2,%3}, [%4];" \
        : "=r"((r)[0]), "=r"((r)[1]), "=r"((r)[2]), "=r"((r)[3]) : "r"(addr))
#define MMAF16(c, a0, a1, a2, a3, b0, b1) \
    asm volatile("mma.sync.aligned.m16n8k16.row.col.f32.f16.f16.f32 " \
        "{%0,%1,%2,%3}, {%4,%5,%6,%7}, {%8,%9}, {%0,%1,%2,%3};" \
        : "+f"((c)[0]), "+f"((c)[1]), "+f"((c)[2]), "+f"((c)[3]) \
        : "r"(a0), "r"(a1), "r"(a2), "r"(a3), "r"(b0), "r"(b1))
#define CPA16(s, g) \
    asm volatile("cp.async.cg.shared.global [%0], [%1], 16;" :: "r"(s), "l"(g))
#define CPC()  asm volatile("cp.async.commit_group;" ::: "memory")
#define CPW1() asm volatile("cp.async.wait_group 1;" ::: "memory")
#define CPW0() asm volatile("cp.async.wait_group 0;" ::: "memory")

__device__ __forceinline__ float phi32(float x) {
    return (x > 0.f) ? (x + 1.f) : __expf(x);
}

// SMEM: 3 B slots x 16KB + A 16KB = 64KB
#define A_STAGE 49152
#define SMEM_TOTAL 65536

// ---------------------------------------------------------------------------
// Kernel A: feature map (fp16x2 h2exp) + mask + [n,l,h,d]->[n,h,l,d].
// Each block covers 32 rows of one (n,h); reduces its K rows into
// g_kpart[block][64]. Zeroes g_rowmax.
// ---------------------------------------------------------------------------
__global__ __launch_bounds__(256) void prep_kernel(
    const float* __restrict__ q, const float* __restrict__ k,
    const float* __restrict__ qm, const float* __restrict__ km)
{
    const int tid = threadIdx.x;
    int idx = blockIdx.x * 256 + tid;              // 8-element chunk index
    if (idx < NROWS) g_rowmax[idx] = 0u;

    int e = idx << 3;
    int d = e & 63;
    int l = (e >> 6) & 2047;
    int h = (e >> 17) & 7;
    int n = e >> 20;
    size_t src = ((((size_t)n * 2048 + l) * 8 + h) << 6) + d;

    float4 q0 = *(const float4*)(q + src);
    float4 q1 = *(const float4*)(q + src + 4);
    float4 k0 = *(const float4*)(k + src);
    float4 k1 = *(const float4*)(k + src + 4);
    const __half2 qm2 = __float2half2_rn(qm[n * 2048 + l]);
    const __half2 km2 = __float2half2_rn(km[n * 2048 + l]);
    const __half2 one2  = __float2half2_rn(1.0f);
    const __half2 zero2 = __float2half2_rn(0.0f);

    float fq[8] = {q0.x, q0.y, q0.z, q0.w, q1.x, q1.y, q1.z, q1.w};
    float fk[8] = {k0.x, k0.y, k0.z, k0.w, k1.x, k1.y, k1.z, k1.w};

    float pk[8];
    uint4 oq, ok;
    uint32_t* pqo = (uint32_t*)&oq;
    uint32_t* pko = (uint32_t*)&ok;
    #pragma unroll
    for (int j = 0; j < 4; j++) {
        __half2 hq = __floats2half2_rn(fq[2*j], fq[2*j+1]);
        __half2 hk = __floats2half2_rn(fk[2*j], fk[2*j+1]);
        __half2 eq = h2exp(hq);
        __half2 ek = h2exp(hk);
        __half2 mq = __hgt2(hq, zero2);
        __half2 mk = __hgt2(hk, zero2);
        __half2 rq = __hfma2(mq, __hsub2(__hadd2(hq, one2), eq), eq);
        __half2 rk = __hfma2(mk, __hsub2(__hadd2(hk, one2), ek), ek);
        rq = __hmul2(rq, qm2);
        rk = __hmul2(rk, km2);
        pqo[j] = *(uint32_t*)&rq;
        pko[j] = *(uint32_t*)&rk;
        float2 fk2 = __half22float2(rk);
        pk[2*j]   = fk2.x;
        pk[2*j+1] = fk2.y;
    }
    ((uint4*)g_Qh)[idx] = oq;
    ((uint4*)g_Kh)[idx] = ok;

    __shared__ float stage[32][72];
    const int row = tid >> 3;
    const int dc  = (tid & 7) * 8;
    #pragma unroll
    for (int j = 0; j < 8; j++) stage[row][dc + j] = pk[j];
    __syncthreads();
    if (tid < 64) {
        float s = 0.f;
        #pragma unroll
        for (int r = 0; r < 32; r++) s += stage[r][tid];
        g_kpart[blockIdx.x * 64 + tid] = s;
    }
}

// ---------------------------------------------------------------------------
// Kernel C: persistent balanced fp16 HMMA score GEMM.
// grid = 296 CTAs; CTA w owns tile-units [w*4096/296, (w+1)*4096/296).
// unit u -> group g=u>>4 (g = nh*16 + ltile), tile t=u&15 (128 s-cols).
// Per segment: stage A, hoist fragments, 3-slot cp.async ring, atomicMax.
// ---------------------------------------------------------------------------
__global__ void __launch_bounds__(256, 2) attn_mma_kernel()
{
    extern __shared__ char sm[];
    const uint32_t smu = smem_u32_of(sm);

    const int tid  = threadIdx.x;
    const int lane = tid & 31;
    const int wid  = tid >> 5;
    const int wx   = wid & 1;
    const int wy   = wid >> 1;

    const int mat    = lane >> 3;
    const int rin    = lane & 7;
    const int a_row  = wy * 32 + (mat & 1) * 8 + rin;
    const int a_kc   = mat >> 1;
    const int b_roff = wx * 64 + (mat >> 1) * 8 + rin;
    const int b_kc   = mat & 1;

    const int u0 = (int)(((long long)blockIdx.x * NUNITS) / NCTA);
    const int u1 = (int)(((long long)(blockIdx.x + 1) * NUNITS) / NCTA);

    int u = u0;
    while (u < u1) {
        const int g   = u >> 4;
        const int tb  = u & 15;
        const int nt  = min(16 - tb, u1 - u);
        const int nh  = g >> 4;
        const int l0  = (g & 15) * 128;

        const char* kh_g = (const char*)(g_Kh + ((size_t)nh * SK + (size_t)tb * 128) * DD);

        __syncthreads();   // previous segment fully done (slots + A reusable)

        // prologue: issue first (up to) 2 tiles
        {
            // tile j (segment-local) -> slot j%3
            #pragma unroll
            for (int kk = 0; kk < 4; kk++) {
                int c = tid + kk * 256;
                int row = c >> 3, dc = c & 7;
                uint32_t sw = row * 128 + ((dc ^ (row & 7)) << 4);
                CPA16(smu + sw, kh_g + c * 16);
            }
            CPC();
            if (nt > 1) {
                #pragma unroll
                for (int kk = 0; kk < 4; kk++) {
                    int c = tid + kk * 256;
                    int row = c >> 3, dc = c & 7;
                    uint32_t sw = row * 128 + ((dc ^ (row & 7)) << 4);
                    CPA16(smu + 16384 + sw, kh_g + 32768 + c * 16);
                }
                CPC();
            }
        }

        // stage A tile, hoist fragments
        {
            const char* qh = (const char*)(g_Qh + ((size_t)nh * LQ + l0) * DD);
            #pragma unroll
            for (int c = tid; c < 1024; c += 256) {
                int row = c >> 3, dc = c & 7;
                uint32_t dst = row * 128 + ((dc ^ (row & 7)) << 4);
                *(uint4*)(sm + A_STAGE + dst) = *(const uint4*)(qh + c * 16);
            }
        }
        __syncthreads();   // A visible

        uint32_t ah[4][2][4];
        #pragma unroll
        for (int ks = 0; ks < 4; ks++)
            #pragma unroll
            for (int i = 0; i < 2; i++) {
                int ar = a_row + 16 * i;
                uint32_t ad = smu + A_STAGE + ar * 128 + (((a_kc + ks * 2) ^ (ar & 7)) << 4);
                LDM4(ah[ks][i], ad);
            }

        float mA[2] = {0.f, 0.f};
        float mB[2] = {0.f, 0.f};

        for (int tt = 0; tt < nt; tt++) {
            if (tt + 1 < nt) { CPW1(); }
            else             { CPW0(); }
            __syncthreads();                 // tile tt visible; tt-1 compute done
            if (tt + 2 < nt) {
                uint32_t bu = smu + ((tt + 2) % 3) * 16384;
                const char* gk = kh_g + (size_t)(tt + 2) * 32768;
                #pragma unroll
                for (int kk = 0; kk < 4; kk++) {
                    int c = tid + kk * 256;
                    int row = c >> 3, dc = c & 7;
                    uint32_t sw = row * 128 + ((dc ^ (row & 7)) << 4);
                    CPA16(bu + sw, gk + c * 16);
                }
                CPC();
            }

            const uint32_t Bu = smu + (tt % 3) * 16384;
            float acc[2][8][4];
            #pragma unroll
            for (int i = 0; i < 2; i++)
                #pragma unroll
                for (int j = 0; j < 8; j++)
                    acc[i][j][0] = acc[i][j][1] = acc[i][j][2] = acc[i][j][3] = 0.f;

            #pragma unroll
            for (int ks = 0; ks < 4; ks++) {
                const int kb = ks * 2;
                #pragma unroll
                for (int jp = 0; jp < 4; jp++) {
                    int br = b_roff + jp * 16;
                    uint32_t bd = Bu + br * 128 + (((b_kc + kb) ^ (br & 7)) << 4);
                    uint32_t rb[4];
                    LDM4(rb, bd);
                    #pragma unroll
                    for (int i = 0; i < 2; i++) {
                        MMAF16(acc[i][jp*2],   ah[ks][i][0], ah[ks][i][1], ah[ks][i][2], ah[ks][i][3], rb[0], rb[1]);
                        MMAF16(acc[i][jp*2+1], ah[ks][i][0], ah[ks][i][1], ah[ks][i][2], ah[ks][i][3], rb[2], rb[3]);
                    }
                }
            }

            #pragma unroll
            for (int i = 0; i < 2; i++)
                #pragma unroll
                for (int j = 0; j < 8; j++) {
                    mA[i] = fmaxf(mA[i], fmaxf(acc[i][j][0], acc[i][j][1]));
                    mB[i] = fmaxf(mB[i], fmaxf(acc[i][j][2], acc[i][j][3]));
                }
        }

        // segment epilogue: reduce across lane%4, atomicMax to gmem
        #pragma unroll
        for (int off = 1; off <= 2; off <<= 1) {
            #pragma unroll
            for (int i = 0; i < 2; i++) {
                mA[i] = fmaxf(mA[i], __shfl_xor_sync(0xffffffff, mA[i], off));
                mB[i] = fmaxf(mB[i], __shfl_xor_sync(0xffffffff, mB[i], off));
            }
        }
        if ((lane & 3) == 0) {
            int r = lane >> 2;
            unsigned int* rmp = g_rowmax + nh * LQ + l0;
            #pragma unroll
            for (int i = 0; i < 2; i++) {
                atomicMax(rmp + wy * 32 + i * 16 + r,     __float_as_uint(mA[i]));
                atomicMax(rmp + wy * 32 + i * 16 + r + 8, __float_as_uint(mB[i]));
            }
        }

        u += nt;
    }
}

// ---------------------------------------------------------------------------
// Kernel D: finalize — ksum reduce + mean (phi recomputed fp32) + gate + out.
// 512 blocks; each block = 64 rows of one nh, 4 threads per row.
// ---------------------------------------------------------------------------
__global__ __launch_bounds__(256) void finalize_kernel(
    const float* __restrict__ queries,
    const float* __restrict__ qmask,
    const float* __restrict__ W,
    const float* __restrict__ bias,
    float* __restrict__ out)
{
    const int tid  = threadIdx.x;
    const int r0   = blockIdx.x * 64;
    const int nh   = r0 >> 11;
    const int n    = nh >> 3;
    const int h    = nh & 7;

    __shared__ float ks_s[64];
    if (tid < 64) {
        const float* kp = g_kpart + (nh << 12) + tid;
        float s = 0.f;
        #pragma unroll 16
        for (int b = 0; b < 64; b++) s += kp[b * 64];
        ks_s[tid] = s;
    }
    __syncthreads();

    const int rrow = tid >> 2;
    const int sub  = tid & 3;
    const int grow = r0 + rrow;
    const int l    = grow & 2047;

    size_t obase = ((((size_t)n * LQ + l) * HH + h) << 6) + sub * 16;
    const float4* qs = (const float4*)(queries + obase);
    float4 v[4];
    v[0] = qs[0]; v[1] = qs[1]; v[2] = qs[2]; v[3] = qs[3];

    float dot = 0.f;
    #pragma unroll
    for (int j = 0; j < 4; j++) {
        const float* f = (const float*)&v[j];
        const int db = sub * 16 + j * 4;
        dot += phi32(f[0]) * ks_s[db];
        dot += phi32(f[1]) * ks_s[db + 1];
        dot += phi32(f[2]) * ks_s[db + 2];
        dot += phi32(f[3]) * ks_s[db + 3];
    }
    dot += __shfl_xor_sync(0xffffffff, dot, 1);
    dot += __shfl_xor_sync(0xffffffff, dot, 2);

    const float qmv = qmask[n * LQ + l];
    float mean = dot * qmv * (1.0f / (float)SK);
    float mx = __uint_as_float(g_rowmax[grow]);
    float lg = fmaf(mean, W[0], fmaf(mx, W[1], bias[0]));
    float gate = 1.0f / (1.0f + __expf(-lg));
    float s = gate * qmv;

    float4* dst = (float4*)(out + obase);
    #pragma unroll
    for (int j = 0; j < 4; j++) {
        float4 w = v[j];
        w.x *= s; w.y *= s; w.z *= s; w.w *= s;
        dst[j] = w;
    }
}

// ---------------------------------------------------------------------------
extern "C" void kernel_launch(void* const* d_in, const int* in_sizes, int n_in,
                              void* d_out, int out_size)
{
    const float* queries = (const float*)d_in[0];
    const float* keys    = (const float*)d_in[1];
    const float* q_mask  = (const float*)d_in[3];
    const float* kv_mask = (const float*)d_in[4];
    const float* W       = (const float*)d_in[5];
    const float* b       = (const float*)d_in[6];
    float* out = (float*)d_out;

    prep_kernel<<<(NHLD / 8) / 256, 256>>>(queries, keys, q_mask, kv_mask);

    cudaFuncSetAttribute(attn_mma_kernel,
                         cudaFuncAttributeMaxDynamicSharedMemorySize, SMEM_TOTAL);
    attn_mma_kernel<<<NCTA, 256, SMEM_TOTAL>>>();

    finalize_kernel<<<NROWS / 64, 256>>>(queries, q_mask, W, b, out);
}